// round 6
// baseline (speedup 1.0000x reference)
#include <cuda_runtime.h>
#include <cuda_bf16.h>
#include <cstdint>

#define NUM_CLASSES 1000
#define FEAT_DIM    512
#define BATCH       32768
#define F4_PER_ROW  (FEAT_DIM / 4)     // 128
// ALPHA = 0.5

// Scratch (device globals, allocation-free). Zero at module load; tail kernel
// restores the accumulating ones (g_hist, g_loss) to zero after each call.
__device__ int   g_hist[NUM_CLASSES];
__device__ int   g_offsets[NUM_CLASSES];
__device__ int   g_cursor[NUM_CLASSES];
__device__ int   g_rowidx[BATCH];
__device__ float g_loss;

// ---------------------------------------------------------------------------
// 1) Histogram of labels (smem-aggregated, then merged to global).
// ---------------------------------------------------------------------------
__global__ void __launch_bounds__(1024) hist_kernel(const int* __restrict__ labels)
{
    __shared__ int sh[NUM_CLASSES];
    for (int i = threadIdx.x; i < NUM_CLASSES; i += 1024) sh[i] = 0;
    __syncthreads();

    const int stride = gridDim.x * 1024;
    for (int r = blockIdx.x * 1024 + threadIdx.x; r < BATCH; r += stride)
        atomicAdd(&sh[labels[r]], 1);
    __syncthreads();

    for (int i = threadIdx.x; i < NUM_CLASSES; i += 1024) {
        int v = sh[i];
        if (v) atomicAdd(&g_hist[i], v);
    }
}

// ---------------------------------------------------------------------------
// 2) Exclusive prefix sum over 1000 counts (single block, Hillis-Steele).
//    Writes g_offsets and primes g_cursor.
// ---------------------------------------------------------------------------
__global__ void __launch_bounds__(1024) scan_kernel()
{
    __shared__ int sh[1024];
    const int t = threadIdx.x;
    sh[t] = (t < NUM_CLASSES) ? g_hist[t] : 0;
    __syncthreads();

    #pragma unroll
    for (int off = 1; off < 1024; off <<= 1) {
        int v = (t >= off) ? sh[t - off] : 0;
        __syncthreads();
        sh[t] += v;
        __syncthreads();
    }
    if (t < NUM_CLASSES) {
        int excl = sh[t] - g_hist[t];
        g_offsets[t] = excl;
        g_cursor[t]  = excl;
    }
}

// ---------------------------------------------------------------------------
// 3) Scatter row indices into class-grouped order.
// ---------------------------------------------------------------------------
__global__ void __launch_bounds__(1024) scatter_kernel(const int* __restrict__ labels)
{
    const int stride = gridDim.x * 1024;
    for (int r = blockIdx.x * 1024 + threadIdx.x; r < BATCH; r += stride) {
        int pos = atomicAdd(&g_cursor[labels[r]], 1);
        g_rowidx[pos] = r;
    }
}

// ---------------------------------------------------------------------------
// 4) Main: one block per class. Accumulates its rows in registers (no fp
//    atomics on the sum path), computes the class's loss contribution via
//      sum||f||^2 - 2<c,s> + cnt*||c||^2
//    and writes the updated center directly to out.
// ---------------------------------------------------------------------------
__global__ void __launch_bounds__(128) class_main_kernel(
    const float* __restrict__ features,
    const float* __restrict__ centers,
    float* __restrict__ out)
{
    const int c = blockIdx.x;
    const int t = threadIdx.x;            // 0..127, one float4 column each
    const int lane = t & 31;
    const int wid  = t >> 5;

    const int cnt = g_hist[c];
    const int off = g_offsets[c];

    const float4* __restrict__ F = reinterpret_cast<const float4*>(features);

    float4 acc = make_float4(0.f, 0.f, 0.f, 0.f);
    float  sumsq = 0.f;

    __shared__ int s_idx[128];

    for (int base = 0; base < cnt; base += 128) {
        const int m = min(128, cnt - base);
        if (t < m) s_idx[t] = g_rowidx[off + base + t];
        __syncthreads();

        int r = 0;
        for (; r + 4 <= m; r += 4) {
            const float4 v0 = F[(size_t)s_idx[r + 0] * F4_PER_ROW + t];
            const float4 v1 = F[(size_t)s_idx[r + 1] * F4_PER_ROW + t];
            const float4 v2 = F[(size_t)s_idx[r + 2] * F4_PER_ROW + t];
            const float4 v3 = F[(size_t)s_idx[r + 3] * F4_PER_ROW + t];
            acc.x += v0.x + v1.x + v2.x + v3.x;
            acc.y += v0.y + v1.y + v2.y + v3.y;
            acc.z += v0.z + v1.z + v2.z + v3.z;
            acc.w += v0.w + v1.w + v2.w + v3.w;
            sumsq += v0.x*v0.x + v0.y*v0.y + v0.z*v0.z + v0.w*v0.w;
            sumsq += v1.x*v1.x + v1.y*v1.y + v1.z*v1.z + v1.w*v1.w;
            sumsq += v2.x*v2.x + v2.y*v2.y + v2.z*v2.z + v2.w*v2.w;
            sumsq += v3.x*v3.x + v3.y*v3.y + v3.z*v3.z + v3.w*v3.w;
        }
        for (; r < m; r++) {
            const float4 v = F[(size_t)s_idx[r] * F4_PER_ROW + t];
            acc.x += v.x; acc.y += v.y; acc.z += v.z; acc.w += v.w;
            sumsq += v.x*v.x + v.y*v.y + v.z*v.z + v.w*v.w;
        }
        __syncthreads();
    }

    // center row + loss assembly
    const float4 cv = reinterpret_cast<const float4*>(centers)[c * F4_PER_ROW + t];
    const float fcnt = (float)cnt;

    float lp = sumsq
             - 2.0f * (cv.x*acc.x + cv.y*acc.y + cv.z*acc.z + cv.w*acc.w)
             + fcnt * (cv.x*cv.x + cv.y*cv.y + cv.z*cv.z + cv.w*cv.w);

    float ox, oy, oz, ow;
    if (cnt > 0) {
        const float inv = 0.5f / fcnt;       // ALPHA = 0.5
        ox = 0.5f * cv.x + acc.x * inv;
        oy = 0.5f * cv.y + acc.y * inv;
        oz = 0.5f * cv.z + acc.z * inv;
        ow = 0.5f * cv.w + acc.w * inv;
    } else {
        ox = cv.x; oy = cv.y; oz = cv.z; ow = cv.w;
    }
    float* o = out + 1 + (size_t)(c * F4_PER_ROW + t) * 4;
    o[0] = ox; o[1] = oy; o[2] = oz; o[3] = ow;

    // ---- block-reduce loss partial -> one atomic per class ----
    #pragma unroll
    for (int s = 16; s > 0; s >>= 1)
        lp += __shfl_xor_sync(0xffffffffu, lp, s);

    __shared__ float wsum[4];
    if (lane == 0) wsum[wid] = lp;
    __syncthreads();
    if (t == 0)
        atomicAdd(&g_loss, wsum[0] + wsum[1] + wsum[2] + wsum[3]);
}

// ---------------------------------------------------------------------------
// 5) Tail: loss scalar; restore g_loss and g_hist to zero for next call.
// ---------------------------------------------------------------------------
__global__ void __launch_bounds__(1024) tail_kernel(float* __restrict__ out)
{
    const int t = threadIdx.x;
    if (t < NUM_CLASSES) g_hist[t] = 0;
    if (t == 0) {
        out[0] = 0.5f * g_loss / (float)BATCH;
        g_loss = 0.0f;
    }
}

extern "C" void kernel_launch(void* const* d_in, const int* in_sizes, int n_in,
                              void* d_out, int out_size)
{
    const float* features = (const float*)d_in[0];
    const int*   labels   = (const int*)d_in[1];
    const float* centers  = (const float*)d_in[2];
    float*       out      = (float*)d_out;

    (void)in_sizes; (void)n_in; (void)out_size;

    hist_kernel<<<16, 1024>>>(labels);
    scan_kernel<<<1, 1024>>>();
    scatter_kernel<<<32, 1024>>>(labels);
    class_main_kernel<<<NUM_CLASSES, 128>>>(features, centers, out);
    tail_kernel<<<1, 1024>>>(out);
}